// round 4
// baseline (speedup 1.0000x reference)
#include <cuda_runtime.h>
#include <cstdint>

#define NQ   512
#define SS   2048
#define DD   128
#define TOPK 32
#define CLS  1000

__device__ float g_summary[NQ * DD];

__device__ __forceinline__ float warp_sum(float v) {
    #pragma unroll
    for (int o = 16; o > 0; o >>= 1) v += __shfl_xor_sync(0xffffffffu, v, o);
    return v;
}

__device__ __forceinline__ void cp_async16(void* smem, const void* gmem) {
    uint32_t s = (uint32_t)__cvta_generic_to_shared(smem);
    asm volatile("cp.async.cg.shared.global [%0], [%1], 16;" :: "r"(s), "l"(gmem));
}

// ---------------------------------------------------------------------------
// K1: logits[n, s] = (q[n] . K[n, s]) / sqrt(D), written to weights_out scratch.
// grid = 1024: CTA j handles query j>>1, half j&1 (1024 seq rows).
// Each warp: autonomous cp.async ring (depth 3, 4 rows/tile), no block barriers.
// ---------------------------------------------------------------------------
__global__ __launch_bounds__(256) void logits_kernel(
    const float* __restrict__ q,
    const float* __restrict__ Kmat,
    float* __restrict__ logits_out)
{
    const int n    = blockIdx.x >> 1;
    const int h    = blockIdx.x & 1;
    const int tid  = threadIdx.x;
    const int warp = tid >> 5;
    const int lane = tid & 31;
    const int row4 = lane >> 3;   // 0..3 row within tile
    const int g    = lane & 7;    // 0..7 group within row

    __shared__ __align__(16) float kring[8][3][4 * DD];   // 48 KB

    const float scale = 0.08838834764831845f; // 1/sqrt(128)

    // q fragment: floats {g*4 + j*32 .. +3}
    float4 qf[4];
    {
        const float* qrow = q + (size_t)n * DD;
        #pragma unroll
        for (int j = 0; j < 4; j++)
            qf[j] = *reinterpret_cast<const float4*>(qrow + g * 4 + j * 32);
    }

    const int   base = h * (SS / 2) + warp * 128;   // this warp's 128 rows
    const float* __restrict__ Ksrc = Kmat + ((size_t)n * SS + base) * DD;
    float* __restrict__ lout = logits_out + (size_t)n * SS + base;

    // issue tile t into ring slot t%3 (4 rows = 512 floats = 128 x 16B)
    #define K1_ISSUE(t)                                                        \
        do {                                                                   \
            float* _dst = kring[warp][(t) % 3];                                \
            const float* _src = Ksrc + (size_t)(t) * 4 * DD;                   \
            _Pragma("unroll")                                                  \
            for (int _i = 0; _i < 4; _i++)                                     \
                cp_async16(&_dst[(lane + 32 * _i) * 4],                        \
                           _src + (lane + 32 * _i) * 4);                       \
            asm volatile("cp.async.commit_group;");                            \
        } while (0)

    K1_ISSUE(0);
    K1_ISSUE(1);

    #pragma unroll 1
    for (int t = 0; t < 32; t++) {
        if (t + 2 < 32) {
            K1_ISSUE(t + 2);
            asm volatile("cp.async.wait_group 2;");
        } else if (t + 1 < 32) {
            asm volatile("cp.async.wait_group 1;");
        } else {
            asm volatile("cp.async.wait_group 0;");
        }
        __syncwarp();  // make all lanes' async copies of tile t visible

        const float* kb = &kring[warp][t % 3][row4 * DD];
        float p = 0.f;
        #pragma unroll
        for (int j = 0; j < 4; j++) {
            float4 kv = *reinterpret_cast<const float4*>(kb + g * 4 + j * 32);
            p += qf[j].x * kv.x + qf[j].y * kv.y + qf[j].z * kv.z + qf[j].w * kv.w;
        }
        p += __shfl_xor_sync(0xffffffffu, p, 1);
        p += __shfl_xor_sync(0xffffffffu, p, 2);
        p += __shfl_xor_sync(0xffffffffu, p, 4);
        if (g == 0) lout[t * 4 + row4] = p * scale;
        __syncwarp();  // tile t consumed; its slot may be overwritten next iter
    }
    #undef K1_ISSUE
}

// ---------------------------------------------------------------------------
// K2: per query — top-32, softmax, weights row (in place), V-gather summary.
// ---------------------------------------------------------------------------
__global__ __launch_bounds__(256) void topk_kernel(
    const float* __restrict__ Vmat,
    float* __restrict__ weights)   // holds raw logits on entry
{
    const int n    = blockIdx.x;
    const int tid  = threadIdx.x;
    const int warp = tid >> 5;
    const int lane = tid & 31;

    __shared__ float logits[SS];
    __shared__ float cand_v[256];
    __shared__ int   cand_i[256];
    __shared__ float s_topv[TOPK];
    __shared__ int   s_topi[TOPK];
    __shared__ float s_w[TOPK];

    const float NEG_INF = __int_as_float(0xff800000);

    // load logits row from global scratch
    {
        const float4* src = reinterpret_cast<const float4*>(weights + (size_t)n * SS);
        float4* dst = reinterpret_cast<float4*>(logits);
        #pragma unroll
        for (int i = tid; i < SS / 4; i += 256) dst[i] = src[i];
    }
    __syncthreads();

    // ---- per-warp top-32 of its 256 logits ----
    {
        float r[8];
        const int base = warp * 256 + lane;
        #pragma unroll
        for (int j = 0; j < 8; j++) r[j] = logits[base + j * 32];

        #pragma unroll 1
        for (int k = 0; k < TOPK; k++) {
            float bv = r[0]; int bj = 0;
            #pragma unroll
            for (int j = 1; j < 8; j++)
                if (r[j] > bv) { bv = r[j]; bj = j; }
            int bi = warp * 256 + bj * 32 + lane;
            #pragma unroll
            for (int o = 16; o > 0; o >>= 1) {
                float ov = __shfl_xor_sync(0xffffffffu, bv, o);
                int   oi = __shfl_xor_sync(0xffffffffu, bi, o);
                if (ov > bv || (ov == bv && oi < bi)) { bv = ov; bi = oi; }
            }
            if (lane == (bi & 31)) {
                int jw = (bi >> 5) & 7;
                #pragma unroll
                for (int j = 0; j < 8; j++)
                    if (j == jw) r[j] = NEG_INF;
            }
            if (lane == 0) { cand_v[warp * 32 + k] = bv; cand_i[warp * 32 + k] = bi; }
        }
    }
    __syncthreads();

    // ---- warp 0: merge 256 candidates -> top-32; softmax ----
    if (warp == 0) {
        float cv[8];
        #pragma unroll
        for (int j = 0; j < 8; j++) cv[j] = cand_v[j * 32 + lane];

        #pragma unroll 1
        for (int k = 0; k < TOPK; k++) {
            float bv = cv[0]; int bj = 0;
            #pragma unroll
            for (int j = 1; j < 8; j++)
                if (cv[j] > bv) { bv = cv[j]; bj = j; }
            int bp = bj * 32 + lane;   // position order == index order on ties
            #pragma unroll
            for (int o = 16; o > 0; o >>= 1) {
                float ov = __shfl_xor_sync(0xffffffffu, bv, o);
                int   op = __shfl_xor_sync(0xffffffffu, bp, o);
                if (ov > bv || (ov == bv && op < bp)) { bv = ov; bp = op; }
            }
            if (lane == (bp & 31)) {
                int jw = bp >> 5;
                #pragma unroll
                for (int j = 0; j < 8; j++)
                    if (j == jw) cv[j] = NEG_INF;
            }
            if (lane == 0) { s_topv[k] = bv; s_topi[k] = cand_i[bp]; }
        }
        __syncwarp();

        float v = s_topv[lane];
        float m = s_topv[0];
        float e = expf(v - m);
        float denom = warp_sum(e);
        s_w[lane] = e / denom;
    }
    __syncthreads();

    // ---- summary gather (tid<128) in parallel with zeroing the row ----
    float acc = 0.f;
    if (tid < DD) {
        #pragma unroll
        for (int i = 0; i < TOPK; i++)
            acc += s_w[i] * Vmat[((size_t)n * SS + s_topi[i]) * DD + tid];
    }
    {
        float4 z = make_float4(0.f, 0.f, 0.f, 0.f);
        float4* l4 = reinterpret_cast<float4*>(logits);
        #pragma unroll
        for (int i = tid; i < SS / 4; i += 256) l4[i] = z;
    }
    __syncthreads();

    if (tid < TOPK) logits[s_topi[tid]] = s_w[tid];
    if (tid < DD)   g_summary[n * DD + tid] = acc;
    __syncthreads();

    // stream the composed weights row back out (coalesced)
    {
        const float4* src = reinterpret_cast<const float4*>(logits);
        float4* dst = reinterpret_cast<float4*>(weights + (size_t)n * SS);
        #pragma unroll
        for (int i = tid; i < SS / 4; i += 256) dst[i] = src[i];
    }
}

// ---------------------------------------------------------------------------
// K3: fused readout GEMMs. 64x64 tile, 4x4 micro-tile, LDS.128.
// blockIdx.x < 16 -> cls (C=1000); 16..17 -> rec (C=128).
// ---------------------------------------------------------------------------
__global__ __launch_bounds__(256) void readout_gemm(
    const float* __restrict__ Wc, const float* __restrict__ bc, float* __restrict__ outc,
    const float* __restrict__ Wr, const float* __restrict__ br, float* __restrict__ outr)
{
    const float* W;  const float* bias;  float* out;  int C;  int cTile;
    if (blockIdx.x < 16) { W = Wc; bias = bc; out = outc; C = CLS; cTile = blockIdx.x * 64; }
    else                 { W = Wr; bias = br; out = outr; C = DD;  cTile = (blockIdx.x - 16) * 64; }

    const int tid = threadIdx.x;
    const int tx  = tid & 15;     // c quad
    const int ty  = tid >> 4;     // n quad
    const int nTile = blockIdx.y * 64;

    __shared__ __align__(16) float As[64][68];   // [k][n], 16B-aligned rows
    __shared__ __align__(16) float Bs[64][68];   // [k][c]

    float acc[4][4];
    #pragma unroll
    for (int i = 0; i < 4; i++)
        #pragma unroll
        for (int j = 0; j < 4; j++) acc[i][j] = 0.f;

    for (int k0 = 0; k0 < DD; k0 += 64) {
        #pragma unroll
        for (int e = 0; e < 4; e++) {
            int linear = tid + e * 256;    // 0..1023
            int k4 = linear >> 6;          // 0..15
            int rr = linear & 63;          // 0..63
            float4 va = *reinterpret_cast<const float4*>(
                g_summary + (nTile + rr) * DD + k0 + k4 * 4);
            As[k4 * 4 + 0][rr] = va.x;
            As[k4 * 4 + 1][rr] = va.y;
            As[k4 * 4 + 2][rr] = va.z;
            As[k4 * 4 + 3][rr] = va.w;
            int cg = cTile + rr;
            float4 vb = make_float4(0.f, 0.f, 0.f, 0.f);
            if (cg < C)
                vb = *reinterpret_cast<const float4*>(W + (size_t)cg * DD + k0 + k4 * 4);
            Bs[k4 * 4 + 0][rr] = vb.x;
            Bs[k4 * 4 + 1][rr] = vb.y;
            Bs[k4 * 4 + 2][rr] = vb.z;
            Bs[k4 * 4 + 3][rr] = vb.w;
        }
        __syncthreads();

        #pragma unroll
        for (int kk = 0; kk < 64; kk++) {
            float4 a = *reinterpret_cast<const float4*>(&As[kk][ty * 4]);
            float4 b = *reinterpret_cast<const float4*>(&Bs[kk][tx * 4]);
            float av[4] = {a.x, a.y, a.z, a.w};
            float bv[4] = {b.x, b.y, b.z, b.w};
            #pragma unroll
            for (int i = 0; i < 4; i++)
                #pragma unroll
                for (int j = 0; j < 4; j++)
                    acc[i][j] += av[i] * bv[j];
        }
        __syncthreads();
    }

    #pragma unroll
    for (int i = 0; i < 4; i++) {
        int nn = nTile + ty * 4 + i;
        #pragma unroll
        for (int j = 0; j < 4; j++) {
            int cg = cTile + tx * 4 + j;
            if (cg < C) out[(size_t)nn * C + cg] = acc[i][j] + bias[cg];
        }
    }
}

extern "C" void kernel_launch(void* const* d_in, const int* in_sizes, int n_in,
                              void* d_out, int out_size) {
    const float* q     = (const float*)d_in[0];
    const float* Kmat  = (const float*)d_in[1];
    const float* Vmat  = (const float*)d_in[2];
    const float* W_cls = (const float*)d_in[3];
    const float* b_cls = (const float*)d_in[4];
    const float* W_rec = (const float*)d_in[5];
    const float* b_rec = (const float*)d_in[6];

    float* out = (float*)d_out;
    float* cls = out;
    float* rec = out + (size_t)NQ * CLS;
    float* wts = rec + (size_t)NQ * DD;

    logits_kernel<<<NQ * 2, 256>>>(q, Kmat, wts);      // wts holds raw logits
    topk_kernel<<<NQ, 256>>>(Vmat, wts);               // in-place -> weights
    readout_gemm<<<dim3(18, NQ / 64), 256>>>(W_cls, b_cls, cls, W_rec, b_rec, rec);
}